// round 2
// baseline (speedup 1.0000x reference)
#include <cuda_runtime.h>
#include <cstdint>

// Problem shape (fixed by the dataset): preds/target = [B=8, C=21, H=512, W=512] fp32.
// Each (b,c) slab = 512*512 = 262144 contiguous floats -> block handles one
// chunk of one slab, so the class index is uniform per block.

#define NCLS 21
#define NSLABS 168            // B * C = 8 * 21
#define SLAB_ELEMS (512 * 512)
#define SLAB_V4 (SLAB_ELEMS / 4)   // 65536 float4 per slab
#define CHUNKS 4
#define CHUNK_V4 (SLAB_V4 / CHUNKS) // 16384 float4 per chunk
#define THREADS 256

__device__ int g_inter[NCLS];
__device__ int g_pred[NCLS];
__device__ int g_targ[NCLS];

__global__ void jidx_zero_kernel() {
    int i = threadIdx.x;
    if (i < NCLS) {
        g_inter[i] = 0;
        g_pred[i]  = 0;
        g_targ[i]  = 0;
    }
}

__global__ __launch_bounds__(THREADS) void jidx_count_kernel(
    const float4* __restrict__ preds4,
    const float4* __restrict__ targ4)
{
    const int slab = blockIdx.y;          // 0..167
    const int cls  = slab % NCLS;
    const size_t base = (size_t)slab * SLAB_V4 + (size_t)blockIdx.x * CHUNK_V4;

    int inter = 0, ps = 0, ts = 0;

    #pragma unroll 4
    for (int i = threadIdx.x; i < CHUNK_V4; i += THREADS) {
        float4 p = preds4[base + i];
        float4 t = targ4[base + i];

        int p0 = p.x >= 0.5f;
        int p1 = p.y >= 0.5f;
        int p2 = p.z >= 0.5f;
        int p3 = p.w >= 0.5f;
        int t0 = t.x == 1.0f;
        int t1 = t.y == 1.0f;
        int t2 = t.z == 1.0f;
        int t3 = t.w == 1.0f;

        ps    += p0 + p1 + p2 + p3;
        ts    += t0 + t1 + t2 + t3;
        inter += (p0 & t0) + (p1 & t1) + (p2 & t2) + (p3 & t3);
    }

    // Warp reduction
    #pragma unroll
    for (int o = 16; o > 0; o >>= 1) {
        inter += __shfl_down_sync(0xffffffffu, inter, o);
        ps    += __shfl_down_sync(0xffffffffu, ps, o);
        ts    += __shfl_down_sync(0xffffffffu, ts, o);
    }

    __shared__ int s_cnt[3];
    if (threadIdx.x < 3) s_cnt[threadIdx.x] = 0;
    __syncthreads();
    if ((threadIdx.x & 31) == 0) {
        atomicAdd(&s_cnt[0], inter);
        atomicAdd(&s_cnt[1], ps);
        atomicAdd(&s_cnt[2], ts);
    }
    __syncthreads();
    if (threadIdx.x == 0) {
        atomicAdd(&g_inter[cls], s_cnt[0]);
        atomicAdd(&g_pred[cls],  s_cnt[1]);
        atomicAdd(&g_targ[cls],  s_cnt[2]);
    }
}

__global__ void jidx_finalize_kernel(float* __restrict__ out) {
    int i = threadIdx.x;
    if (i < NCLS) {
        float inter = (float)g_inter[i];
        float uni   = (float)(g_pred[i] + g_targ[i] - g_inter[i]);
        out[i] = (uni == 0.0f) ? __int_as_float(0x7fc00000)  // NaN
                               : inter / fmaxf(uni, 1.0f);
    }
}

extern "C" void kernel_launch(void* const* d_in, const int* in_sizes, int n_in,
                              void* d_out, int out_size) {
    const float4* preds4 = (const float4*)d_in[0];
    const float4* targ4  = (const float4*)d_in[1];
    float* out = (float*)d_out;

    jidx_zero_kernel<<<1, 32>>>();
    dim3 grid(CHUNKS, NSLABS);
    jidx_count_kernel<<<grid, THREADS>>>(preds4, targ4);
    jidx_finalize_kernel<<<1, 32>>>(out);
}

// round 3
// speedup vs baseline: 1.0305x; 1.0305x over previous
#include <cuda_runtime.h>
#include <cstdint>

// preds/target = [B=8, C=21, H=512, W=512] fp32, contiguous.
// Each (b,c) slab = 262144 contiguous floats; block handles one chunk of one
// slab so the class is uniform per block. Single fused kernel: count ->
// last-block finalize -> self-reset (graph-replay safe, deterministic).

#define NCLS 21
#define NSLABS 168                  // B * C
#define SLAB_V4 (512 * 512 / 4)     // 65536 float4 per slab
#define CHUNKS 4
#define CHUNK_V4 (SLAB_V4 / CHUNKS) // 16384 float4 per chunk
#define THREADS 256
#define TOTAL_BLOCKS (CHUNKS * NSLABS)  // 672

__device__ int g_inter[NCLS];
__device__ int g_pred[NCLS];
__device__ int g_targ[NCLS];
__device__ unsigned int g_done;     // zero-initialized; reset by last block

__global__ __launch_bounds__(THREADS) void jidx_fused_kernel(
    const float4* __restrict__ preds4,
    const float4* __restrict__ targ4,
    float* __restrict__ out)
{
    const int slab = blockIdx.y;          // 0..167
    const int cls  = slab % NCLS;
    const size_t base = (size_t)slab * SLAB_V4 + (size_t)blockIdx.x * CHUNK_V4;

    int inter = 0, ps = 0, ts = 0;

    #pragma unroll 4
    for (int i = threadIdx.x; i < CHUNK_V4; i += THREADS) {
        float4 p = preds4[base + i];
        float4 t = targ4[base + i];

        int p0 = p.x >= 0.5f;
        int p1 = p.y >= 0.5f;
        int p2 = p.z >= 0.5f;
        int p3 = p.w >= 0.5f;
        int t0 = t.x == 1.0f;
        int t1 = t.y == 1.0f;
        int t2 = t.z == 1.0f;
        int t3 = t.w == 1.0f;

        ps    += p0 + p1 + p2 + p3;
        ts    += t0 + t1 + t2 + t3;
        inter += (p0 & t0) + (p1 & t1) + (p2 & t2) + (p3 & t3);
    }

    // Warp reduction
    #pragma unroll
    for (int o = 16; o > 0; o >>= 1) {
        inter += __shfl_down_sync(0xffffffffu, inter, o);
        ps    += __shfl_down_sync(0xffffffffu, ps, o);
        ts    += __shfl_down_sync(0xffffffffu, ts, o);
    }

    __shared__ int s_cnt[3];
    __shared__ int s_last;
    if (threadIdx.x < 3) s_cnt[threadIdx.x] = 0;
    __syncthreads();
    if ((threadIdx.x & 31) == 0) {
        atomicAdd(&s_cnt[0], inter);
        atomicAdd(&s_cnt[1], ps);
        atomicAdd(&s_cnt[2], ts);
    }
    __syncthreads();

    if (threadIdx.x == 0) {
        atomicAdd(&g_inter[cls], s_cnt[0]);
        atomicAdd(&g_pred[cls],  s_cnt[1]);
        atomicAdd(&g_targ[cls],  s_cnt[2]);
        __threadfence();                       // publish counts before done++
        unsigned int t = atomicAdd(&g_done, 1u);
        s_last = (t == (unsigned int)(TOTAL_BLOCKS - 1));
    }
    __syncthreads();

    if (s_last) {
        __threadfence();                       // acquire all published counts
        if (threadIdx.x < NCLS) {
            int i = threadIdx.x;
            float fi  = (float)g_inter[i];
            float uni = (float)(g_pred[i] + g_targ[i] - g_inter[i]);
            out[i] = (uni == 0.0f) ? __int_as_float(0x7fc00000)  // NaN
                                   : fi / fmaxf(uni, 1.0f);
            // self-reset for the next graph replay
            g_inter[i] = 0;
            g_pred[i]  = 0;
            g_targ[i]  = 0;
        }
        if (threadIdx.x == 0) g_done = 0u;
    }
}

extern "C" void kernel_launch(void* const* d_in, const int* in_sizes, int n_in,
                              void* d_out, int out_size) {
    const float4* preds4 = (const float4*)d_in[0];
    const float4* targ4  = (const float4*)d_in[1];
    float* out = (float*)d_out;

    dim3 grid(CHUNKS, NSLABS);
    jidx_fused_kernel<<<grid, THREADS>>>(preds4, targ4, out);
}

// round 4
// speedup vs baseline: 1.0357x; 1.0050x over previous
#include <cuda_runtime.h>
#include <cstdint>

// preds/target = [B=8, C=21, H=512, W=512] fp32, contiguous.
// Work decomposed into 5376 units of 2048 float4 (32 units per (b,c) slab,
// so class is uniform per unit). Grid = 148 SMs * 8 blocks = 1184 -> one
// perfect full-residency wave; blocks grid-stride over units.
// Fused: count -> last-block finalize -> self-reset (graph-replay safe).

#define NCLS 21
#define UNITS_PER_SLAB 32
#define UNIT_V4 2048                    // 65536 / 32
#define TOTAL_UNITS (168 * UNITS_PER_SLAB)  // 5376
#define THREADS 256
#define GRID_BLOCKS (148 * 8)           // 1184

__device__ int g_inter[NCLS];
__device__ int g_pred[NCLS];
__device__ int g_targ[NCLS];
__device__ unsigned int g_done;         // zero-init; reset by last block

__global__ __launch_bounds__(THREADS, 8) void jidx_fused_kernel(
    const float4* __restrict__ preds4,
    const float4* __restrict__ targ4,
    float* __restrict__ out)
{
    __shared__ int s_cnt[3];
    __shared__ int s_last;

    for (int u = blockIdx.x; u < TOTAL_UNITS; u += GRID_BLOCKS) {
        const int cls = (u >> 5) % NCLS;             // slab = u / 32
        const size_t base = (size_t)u * UNIT_V4;

        int inter = 0, ps = 0, ts = 0;

        #pragma unroll 4
        for (int i = threadIdx.x; i < UNIT_V4; i += THREADS) {
            float4 p = __ldcs(&preds4[base + i]);
            float4 t = __ldcs(&targ4[base + i]);

            int p0 = p.x >= 0.5f;
            int p1 = p.y >= 0.5f;
            int p2 = p.z >= 0.5f;
            int p3 = p.w >= 0.5f;
            int t0 = t.x == 1.0f;
            int t1 = t.y == 1.0f;
            int t2 = t.z == 1.0f;
            int t3 = t.w == 1.0f;

            ps    += p0 + p1 + p2 + p3;
            ts    += t0 + t1 + t2 + t3;
            inter += (p0 & t0) + (p1 & t1) + (p2 & t2) + (p3 & t3);
        }

        // Warp reduction
        #pragma unroll
        for (int o = 16; o > 0; o >>= 1) {
            inter += __shfl_down_sync(0xffffffffu, inter, o);
            ps    += __shfl_down_sync(0xffffffffu, ps, o);
            ts    += __shfl_down_sync(0xffffffffu, ts, o);
        }

        if (threadIdx.x < 3) s_cnt[threadIdx.x] = 0;
        __syncthreads();
        if ((threadIdx.x & 31) == 0) {
            atomicAdd(&s_cnt[0], inter);
            atomicAdd(&s_cnt[1], ps);
            atomicAdd(&s_cnt[2], ts);
        }
        __syncthreads();
        if (threadIdx.x == 0) {
            atomicAdd(&g_inter[cls], s_cnt[0]);
            atomicAdd(&g_pred[cls],  s_cnt[1]);
            atomicAdd(&g_targ[cls],  s_cnt[2]);
        }
        __syncthreads();   // protect s_cnt reuse next unit
    }

    // Completion protocol: one arrival per block after all its units.
    if (threadIdx.x == 0) {
        __threadfence();                 // publish counts before done++
        unsigned int t = atomicAdd(&g_done, 1u);
        s_last = (t == (unsigned int)(GRID_BLOCKS - 1));
    }
    __syncthreads();

    if (s_last) {
        __threadfence();                 // acquire all published counts
        if (threadIdx.x < NCLS) {
            int i = threadIdx.x;
            float fi  = (float)g_inter[i];
            float uni = (float)(g_pred[i] + g_targ[i] - g_inter[i]);
            out[i] = (uni == 0.0f) ? __int_as_float(0x7fc00000)  // NaN
                                   : fi / fmaxf(uni, 1.0f);
            // self-reset for next graph replay
            g_inter[i] = 0;
            g_pred[i]  = 0;
            g_targ[i]  = 0;
        }
        if (threadIdx.x == 0) g_done = 0u;
    }
}

extern "C" void kernel_launch(void* const* d_in, const int* in_sizes, int n_in,
                              void* d_out, int out_size) {
    const float4* preds4 = (const float4*)d_in[0];
    const float4* targ4  = (const float4*)d_in[1];
    float* out = (float*)d_out;

    jidx_fused_kernel<<<GRID_BLOCKS, THREADS>>>(preds4, targ4, out);
}